// round 5
// baseline (speedup 1.0000x reference)
#include <cuda_runtime.h>
#include <cuda_bf16.h>
#include <math.h>
#include <stdint.h>

// Problem constants
#define BB 2
#define SS 2048
#define DD 1024
#define HH 16
#define HD 64
#define RA 32
#define RF 512
#define RO 512
#define INTER 4096
#define BS (BB * SS)          // 4096 rows
#define CLAMP_V 1.0e6f
#define LN_EPS 1e-5f

typedef __nv_bfloat16 bf16;

// ---------------------------------------------------------------------------
// Scratch (device globals: allocation-free)
// ---------------------------------------------------------------------------
__device__ __align__(256) bf16 g_normh[BS * DD];
__device__ __align__(256) bf16 g_norml[BS * DD];
__device__ __align__(256) float g_Tq[BS * (HH * RA)];
__device__ __align__(256) float g_Tk[BS * (HH * RA)];
__device__ __align__(256) float g_Tv[BS * (HH * RA)];
__device__ __align__(256) bf16 g_qh[BB * HH * SS * HD];
__device__ __align__(256) bf16 g_ql[BB * HH * SS * HD];
__device__ __align__(256) bf16 g_kh[BB * HH * SS * HD];
__device__ __align__(256) bf16 g_kl[BB * HH * SS * HD];
__device__ __align__(256) bf16 g_vth[BB * HH * HD * SS];
__device__ __align__(256) bf16 g_vtl[BB * HH * HD * SS];
__device__ __align__(256) bf16 g_attnh[BS * DD];
__device__ __align__(256) bf16 g_attnl[BS * DD];
__device__ __align__(256) bf16 g_tmph[BS * 512];
__device__ __align__(256) bf16 g_tmpl[BS * 512];
__device__ __align__(256) bf16 g_ffh[BS * INTER];
__device__ __align__(256) bf16 g_ffl[BS * INTER];
__device__ __align__(256) float g_h[BS * DD];
// split-weight pool (7,864,320 elems)
#define WOFF_QV   0
#define WOFF_KV   524288
#define WOFF_VV   1048576
#define WOFF_OV   1572864
#define WOFF_OU   2097152
#define WOFF_F1V  2621440
#define WOFF_F1U  3145728
#define WOFF_F2V  5242880
#define WOFF_F2U  7340032
#define WPOOL_SZ  7864320
__device__ __align__(256) bf16 g_wh[WPOOL_SZ];
__device__ __align__(256) bf16 g_wl[WPOOL_SZ];

// ---------------------------------------------------------------------------
// helpers
// ---------------------------------------------------------------------------
__device__ __forceinline__ void mma16816(float* c, const uint32_t* a, const uint32_t* b) {
    asm volatile(
        "mma.sync.aligned.m16n8k16.row.col.f32.bf16.bf16.f32 "
        "{%0,%1,%2,%3}, {%4,%5,%6,%7}, {%8,%9}, {%0,%1,%2,%3};"
        : "+f"(c[0]), "+f"(c[1]), "+f"(c[2]), "+f"(c[3])
        : "r"(a[0]), "r"(a[1]), "r"(a[2]), "r"(a[3]), "r"(b[0]), "r"(b[1]));
}
__device__ __forceinline__ void packsplit(float f0, float f1, uint32_t& hi, uint32_t& lo) {
    __nv_bfloat162 h = __floats2bfloat162_rn(f0, f1);
    hi = *reinterpret_cast<uint32_t*>(&h);
    __nv_bfloat162 l = __floats2bfloat162_rn(f0 - __bfloat162float(h.x),
                                             f1 - __bfloat162float(h.y));
    lo = *reinterpret_cast<uint32_t*>(&l);
}
__device__ __forceinline__ void split8(const float4& f0, const float4& f1,
                                       uint4& hi, uint4& lo) {
    float f[8] = {f0.x, f0.y, f0.z, f0.w, f1.x, f1.y, f1.z, f1.w};
    uint32_t h[4], l[4];
#pragma unroll
    for (int j = 0; j < 4; j++) packsplit(f[2 * j], f[2 * j + 1], h[j], l[j]);
    hi = make_uint4(h[0], h[1], h[2], h[3]);
    lo = make_uint4(l[0], l[1], l[2], l[3]);
}
#define CP_ASYNC16(dst, src) \
    asm volatile("cp.async.cg.shared.global [%0], [%1], 16;" :: "r"(dst), "l"(src) : "memory")
#define CP_COMMIT() asm volatile("cp.async.commit_group;" ::: "memory")
#define CP_WAIT0() asm volatile("cp.async.wait_group 0;" ::: "memory")
#define CP_WAIT1() asm volatile("cp.async.wait_group 1;" ::: "memory")
#define CP_WAIT2() asm volatile("cp.async.wait_group 2;" ::: "memory")
#define LDSM4(r, addr) \
    asm volatile("ldmatrix.sync.aligned.m8n8.x4.shared.b16 {%0,%1,%2,%3}, [%4];" \
        : "=r"((r)[0]), "=r"((r)[1]), "=r"((r)[2]), "=r"((r)[3]) : "r"(addr))
#define LDSM2(r, addr) \
    asm volatile("ldmatrix.sync.aligned.m8n8.x2.shared.b16 {%0,%1}, [%2];" \
        : "=r"((r)[0]), "=r"((r)[1]) : "r"(addr))
__device__ __forceinline__ uint32_t smem_u32(const void* p) {
    uint32_t a;
    asm("{ .reg .u64 t; cvta.to.shared.u64 t, %1; cvt.u32.u64 %0, t; }" : "=r"(a) : "l"(p));
    return a;
}

// ---------------------------------------------------------------------------
// weight split kernel: fp32 -> bf16 hi/lo
// ---------------------------------------------------------------------------
__global__ __launch_bounds__(256) void wsplit_kernel(
    const float* __restrict__ x, bf16* __restrict__ hi, bf16* __restrict__ lo, int n8)
{
    int i = blockIdx.x * 256 + threadIdx.x;
    if (i >= n8) return;
    float4 f0 = *reinterpret_cast<const float4*>(x + i * 8);
    float4 f1 = *reinterpret_cast<const float4*>(x + i * 8 + 4);
    uint4 h, l;
    split8(f0, f1, h, l);
    *reinterpret_cast<uint4*>(hi + i * 8) = h;
    *reinterpret_cast<uint4*>(lo + i * 8) = l;
}

// ---------------------------------------------------------------------------
// bf16-input GEMM: C[M,N] = A[M,K] @ W[N,K]^T (3-term split: AhBh+AlBh+AhBl)
// 128x128 tile, BK=32, 3-stage cp.async pipeline, ldmatrix fragments.
// OUTBF16: write bf16 hi/lo (Ch/Cl) else fp32 C.
// EPI: 0 = (+bias); 1 = (+bias)+exact GELU; 2 = (+bias)+residual(fp32)
// smem stage: Ah,Al,Bh,Bl each 128 rows x 80B = 10240B -> 40960B/stage, 3 stages.
// ---------------------------------------------------------------------------
#define BG_ARR   10240
#define BG_STAGE 40960
#define BG_SMEM  (3 * BG_STAGE)

__device__ __forceinline__ void bg_load(
    uint32_t stg, const bf16* Ah, const bf16* Al, const bf16* Bh, const bf16* Bl,
    int K, int k0, int tid)
{
#pragma unroll
    for (int i = 0; i < 8; i++) {
        int idx = tid + 256 * i;     // 2048 chunks of 16B
        int a = idx >> 9;
        int rem = idx & 511;
        int row = rem >> 2;
        int c = rem & 3;
        uint32_t dst = stg + (uint32_t)a * BG_ARR + row * 80 + c * 16;
        const bf16* src;
        if (a == 0)      src = Ah + (size_t)row * K + k0 + c * 8;
        else if (a == 1) src = Al + (size_t)row * K + k0 + c * 8;
        else if (a == 2) src = Bh + (size_t)row * K + k0 + c * 8;
        else             src = Bl + (size_t)row * K + k0 + c * 8;
        CP_ASYNC16(dst, src);
    }
}

template <int OUTBF16, int EPI>
__global__ __launch_bounds__(256) void bgemm(
    int M, int N, int K,
    const bf16* __restrict__ Ah, const bf16* __restrict__ Al,
    const bf16* __restrict__ Wh, const bf16* __restrict__ Wl,
    const float* __restrict__ bias, const float* __restrict__ res,
    float* __restrict__ C, bf16* __restrict__ Ch, bf16* __restrict__ Cl)
{
    extern __shared__ char sm[];
    const uint32_t sb = smem_u32(sm);
    const int tid = threadIdx.x;
    const int lane = tid & 31;
    const int warp = tid >> 5;
    const int wm = (warp >> 2) * 64;
    const int wn = (warp & 3) * 32;
    const int bm = blockIdx.y * 128;
    const int bn = blockIdx.x * 128;

    const bf16* Ab  = Ah + (size_t)bm * K;
    const bf16* Alb = Al + (size_t)bm * K;
    const bf16* Wb  = Wh + (size_t)bn * K;
    const bf16* Wlb = Wl + (size_t)bn * K;
    const int nchunks = K >> 5;

    float acc[4][4][4];
#pragma unroll
    for (int i = 0; i < 4; i++)
#pragma unroll
        for (int j = 0; j < 4; j++)
#pragma unroll
            for (int k = 0; k < 4; k++) acc[i][j][k] = 0.f;

    // prologue: 3 stages
#pragma unroll
    for (int s = 0; s < 3; s++) {
        bg_load(sb + s * BG_STAGE, Ab, Alb, Wb, Wlb, K, s << 5, tid);
        CP_COMMIT();
    }

    // precomputed fragment smem addresses (stage-relative)
    const uint32_t aoff = (uint32_t)((wm + (lane & 15)) * 80 + (lane >> 4) * 16);
    const uint32_t boff = (uint32_t)(2 * BG_ARR + (wn + (lane & 7)) * 80 + ((lane >> 3) & 1) * 16);

    int slot = 0;
    for (int c = 0; c < nchunks; c++) {
        CP_WAIT2();
        __syncthreads();
        const uint32_t stg = sb + (uint32_t)slot * BG_STAGE;

#pragma unroll
        for (int kk = 0; kk < 2; kk++) {
            const uint32_t kb = kk * 32;
            uint32_t ah[4][4], al[4][4], bh[4][2], bl[4][2];
#pragma unroll
            for (int mt = 0; mt < 4; mt++) {
                uint32_t ad = stg + aoff + mt * (16 * 80) + kb;
                LDSM4(ah[mt], ad);
                LDSM4(al[mt], ad + BG_ARR);
            }
#pragma unroll
            for (int nt = 0; nt < 4; nt++) {
                uint32_t bd = stg + boff + nt * (8 * 80) + kb;
                LDSM2(bh[nt], bd);
                LDSM2(bl[nt], bd + BG_ARR);
            }
#pragma unroll
            for (int mt = 0; mt < 4; mt++)
#pragma unroll
                for (int nt = 0; nt < 4; nt++)
                    mma16816(acc[mt][nt], ah[mt], bh[nt]);
#pragma unroll
            for (int mt = 0; mt < 4; mt++)
#pragma unroll
                for (int nt = 0; nt < 4; nt++)
                    mma16816(acc[mt][nt], al[mt], bh[nt]);
#pragma unroll
            for (int mt = 0; mt < 4; mt++)
#pragma unroll
                for (int nt = 0; nt < 4; nt++)
                    mma16816(acc[mt][nt], ah[mt], bl[nt]);
        }
        __syncthreads();
        if (c + 3 < nchunks)
            bg_load(sb + (uint32_t)slot * BG_STAGE, Ab, Alb, Wb, Wlb, K, (c + 3) << 5, tid);
        CP_COMMIT();                    // empty group ok: keeps wait counting exact
        slot = (slot == 2) ? 0 : slot + 1;
    }

    // epilogue
#pragma unroll
    for (int mt = 0; mt < 4; mt++) {
#pragma unroll
        for (int nt = 0; nt < 4; nt++) {
            const float* cc = acc[mt][nt];
            const int gr = bm + wm + mt * 16 + (lane >> 2);
            const int gc = bn + wn + nt * 8 + (lane & 3) * 2;
            float b0 = 0.f, b1 = 0.f;
            if (bias) { b0 = bias[gc]; b1 = bias[gc + 1]; }
#pragma unroll
            for (int half = 0; half < 2; half++) {
                const int row = gr + half * 8;
                float v0 = cc[half * 2 + 0] + b0;
                float v1 = cc[half * 2 + 1] + b1;
                if (EPI == 1) {
                    v0 = 0.5f * v0 * (1.0f + erff(v0 * 0.70710678118654752f));
                    v1 = 0.5f * v1 * (1.0f + erff(v1 * 0.70710678118654752f));
                }
                if (EPI == 2) {
                    float2 r2 = *reinterpret_cast<const float2*>(res + (size_t)row * N + gc);
                    v0 += r2.x; v1 += r2.y;
                }
                if (OUTBF16) {
                    uint32_t hi, lo;
                    packsplit(v0, v1, hi, lo);
                    *reinterpret_cast<uint32_t*>(Ch + (size_t)row * N + gc) = hi;
                    *reinterpret_cast<uint32_t*>(Cl + (size_t)row * N + gc) = lo;
                } else {
                    *reinterpret_cast<float2*>(C + (size_t)row * N + gc) = make_float2(v0, v1);
                }
            }
        }
    }
}

// ---------------------------------------------------------------------------
// LayerNorm -> bf16 hi/lo output
// ---------------------------------------------------------------------------
__global__ __launch_bounds__(256) void ln_kernel(
    const float* __restrict__ x, const float* __restrict__ w,
    const float* __restrict__ b, bf16* __restrict__ oh, bf16* __restrict__ ol)
{
    __shared__ float warpred[8];
    __shared__ float s_mean, s_var;
    const int row = blockIdx.x;
    const int tid = threadIdx.x;
    const float* xr = x + (size_t)row * DD;

    float4 v = *reinterpret_cast<const float4*>(xr + tid * 4);
    float local = v.x + v.y + v.z + v.w;
#pragma unroll
    for (int off = 16; off > 0; off >>= 1)
        local += __shfl_xor_sync(0xffffffffu, local, off);
    if ((tid & 31) == 0) warpred[tid >> 5] = local;
    __syncthreads();
    if (tid == 0) {
        float s = 0.f;
#pragma unroll
        for (int i = 0; i < 8; i++) s += warpred[i];
        s_mean = s * (1.0f / DD);
    }
    __syncthreads();
    const float mean = s_mean;

    float d0 = v.x - mean, d1 = v.y - mean, d2 = v.z - mean, d3 = v.w - mean;
    local = d0 * d0 + d1 * d1 + d2 * d2 + d3 * d3;
#pragma unroll
    for (int off = 16; off > 0; off >>= 1)
        local += __shfl_xor_sync(0xffffffffu, local, off);
    if ((tid & 31) == 0) warpred[tid >> 5] = local;
    __syncthreads();
    if (tid == 0) {
        float s = 0.f;
#pragma unroll
        for (int i = 0; i < 8; i++) s += warpred[i];
        s_var = s * (1.0f / DD);
    }
    __syncthreads();
    const float rstd = rsqrtf(s_var + LN_EPS);

    float4 wv = *reinterpret_cast<const float4*>(w + tid * 4);
    float4 bv = *reinterpret_cast<const float4*>(b + tid * 4);
    float y0 = d0 * rstd * wv.x + bv.x;
    float y1 = d1 * rstd * wv.y + bv.y;
    float y2 = d2 * rstd * wv.z + bv.z;
    float y3 = d3 * rstd * wv.w + bv.w;
    uint32_t h0, l0, h1, l1;
    packsplit(y0, y1, h0, l0);
    packsplit(y2, y3, h1, l1);
    size_t base = (size_t)row * DD + tid * 4;
    *reinterpret_cast<uint32_t*>(oh + base) = h0;
    *reinterpret_cast<uint32_t*>(oh + base + 2) = h1;
    *reinterpret_cast<uint32_t*>(ol + base) = l0;
    *reinterpret_cast<uint32_t*>(ol + base + 2) = l1;
}

// ---------------------------------------------------------------------------
// Per-head U projection -> bf16 hi/lo. TRANS=0: [B,H,S,HD]; 1: [B,H,HD,S]
// ---------------------------------------------------------------------------
template <int TRANS>
__global__ __launch_bounds__(256) void uproj_kernel(
    const float* __restrict__ T, const float* __restrict__ U,
    const float* __restrict__ bias,
    bf16* __restrict__ oh, bf16* __restrict__ ol)
{
    __shared__ float Us[HD][RA + 1];
    __shared__ float Ts[64][RA + 1];
    const int head = blockIdx.y;
    const int s0 = blockIdx.x * 64;
    const int tid = threadIdx.x;

#pragma unroll
    for (int i = 0; i < 8; i++) {
        int idx = tid + 256 * i;
        Us[idx >> 5][idx & 31] = U[(size_t)head * (HD * RA) + idx];
    }
#pragma unroll
    for (int i = 0; i < 8; i++) {
        int idx = tid + 256 * i;
        int sl = idx >> 5, r = idx & 31;
        Ts[sl][r] = T[(size_t)(s0 + sl) * (HH * RA) + head * RA + r];
    }
    __syncthreads();

    const int sl = tid >> 2;
    const int eg = tid & 3;
    float accv[16];
#pragma unroll
    for (int i = 0; i < 16; i++) accv[i] = 0.f;
#pragma unroll
    for (int r = 0; r < RA; r++) {
        float t = Ts[sl][r];
#pragma unroll
        for (int i = 0; i < 16; i++)
            accv[i] += t * Us[eg + 4 * i][r];
    }

    const int bs = s0 + sl;
    const int bb = bs / SS;
    const int s = bs - bb * SS;
#pragma unroll
    for (int i = 0; i < 16; i++) {
        int e = eg + 4 * i;
        float v = accv[i] + bias[head * HD + e];
        v = fminf(fmaxf(v, -CLAMP_V), CLAMP_V);
        bf16 hh = __float2bfloat16(v);
        bf16 ll = __float2bfloat16(v - __bfloat162float(hh));
        size_t idx;
        if (TRANS)
            idx = ((size_t)(bb * HH + head) * HD + e) * SS + s;
        else
            idx = ((size_t)(bb * HH + head) * SS + s) * HD + e;
        oh[idx] = hh;
        ol[idx] = ll;
    }
}

// ---------------------------------------------------------------------------
// Flash attention (mma.sync bf16, 3-term splits), epilogue -> bf16 hi/lo
// ---------------------------------------------------------------------------
#define AT_ROWB 144
#define AT_Q_BYTES (128 * AT_ROWB)
#define AT_KV_BYTES (64 * AT_ROWB)
#define AT_STG_BYTES (4 * AT_KV_BYTES)
#define AT_STG0 (2 * AT_Q_BYTES)
#define AT_SMEM (AT_STG0 + 2 * AT_STG_BYTES)

__device__ __forceinline__ void attn_load_kv(
    uint32_t stg_sb, const bf16* kh, const bf16* kl,
    const bf16* vth, const bf16* vtl, int bh, int jt, int tid)
{
#pragma unroll
    for (int i = 0; i < 8; i++) {
        int idx = tid + 256 * i;
        int a = idx >> 9;
        int rem = idx & 511;
        int row = rem >> 3;
        int c = rem & 7;
        uint32_t dst = stg_sb + (uint32_t)a * AT_KV_BYTES + row * AT_ROWB + c * 16;
        const bf16* src;
        if (a == 0)      src = kh  + ((size_t)bh * SS + jt * 64 + row) * HD + c * 8;
        else if (a == 1) src = kl  + ((size_t)bh * SS + jt * 64 + row) * HD + c * 8;
        else if (a == 2) src = vth + ((size_t)bh * HD + row) * SS + jt * 64 + c * 8;
        else             src = vtl + ((size_t)bh * HD + row) * SS + jt * 64 + c * 8;
        CP_ASYNC16(dst, src);
    }
}

__global__ __launch_bounds__(256) void attn_mma_kernel(
    const bf16* __restrict__ qh, const bf16* __restrict__ ql,
    const bf16* __restrict__ kh, const bf16* __restrict__ kl,
    const bf16* __restrict__ vth, const bf16* __restrict__ vtl,
    bf16* __restrict__ Oh, bf16* __restrict__ Ol)
{
    extern __shared__ char asmm[];
    const uint32_t sb = smem_u32(asmm);
    const int bh = blockIdx.y;
    const int qt = blockIdx.x;
    const int tid = threadIdx.x;
    const int lane = tid & 31;
    const int warp = tid >> 5;
    const int g = lane >> 2;
    const int t = lane & 3;
    const int wm = warp * 16;

#pragma unroll
    for (int i = 0; i < 8; i++) {
        int idx = tid + 256 * i;
        int a = idx >> 10;
        int rem = idx & 1023;
        int row = rem >> 3;
        int c = rem & 7;
        uint32_t dst = sb + (uint32_t)a * AT_Q_BYTES + row * AT_ROWB + c * 16;
        const bf16* src = (a ? ql : qh) + ((size_t)bh * SS + qt * 128 + row) * HD + c * 8;
        CP_ASYNC16(dst, src);
    }
    attn_load_kv(sb + AT_STG0, kh, kl, vth, vtl, bh, 0, tid);
    CP_COMMIT();

    float m_a = -1e30f, m_b = -1e30f, l_a = 0.f, l_b = 0.f;
    float oacc[8][4];
#pragma unroll
    for (int i = 0; i < 8; i++)
#pragma unroll
        for (int j = 0; j < 4; j++) oacc[i][j] = 0.f;

    const int ntiles = 2 * qt + 2;
    const int rowa = qt * 128 + wm + g;
    const int rowb = rowa + 8;

    for (int jt = 0; jt < ntiles; jt++) {
        if (jt + 1 < ntiles) {
            attn_load_kv(sb + AT_STG0 + ((jt + 1) & 1) * AT_STG_BYTES,
                         kh, kl, vth, vtl, bh, jt + 1, tid);
            CP_COMMIT();
            CP_WAIT1();
        } else {
            CP_WAIT0();
        }
        __syncthreads();

        const char* stg = asmm + AT_STG0 + (jt & 1) * AT_STG_BYTES;
        const char* qhB = asmm;
        const char* qlB = asmm + AT_Q_BYTES;

        float sacc[8][4];
#pragma unroll
        for (int i = 0; i < 8; i++)
#pragma unroll
            for (int j = 0; j < 4; j++) sacc[i][j] = 0.f;

#pragma unroll
        for (int ks = 0; ks < 4; ks++) {
            const int ab = (wm + g) * AT_ROWB + ks * 32 + t * 4;
            uint32_t ah[4], al[4];
            ah[0] = *reinterpret_cast<const uint32_t*>(qhB + ab);
            ah[1] = *reinterpret_cast<const uint32_t*>(qhB + ab + 8 * AT_ROWB);
            ah[2] = *reinterpret_cast<const uint32_t*>(qhB + ab + 16);
            ah[3] = *reinterpret_cast<const uint32_t*>(qhB + ab + 8 * AT_ROWB + 16);
            al[0] = *reinterpret_cast<const uint32_t*>(qlB + ab);
            al[1] = *reinterpret_cast<const uint32_t*>(qlB + ab + 8 * AT_ROWB);
            al[2] = *reinterpret_cast<const uint32_t*>(qlB + ab + 16);
            al[3] = *reinterpret_cast<const uint32_t*>(qlB + ab + 8 * AT_ROWB + 16);
#pragma unroll
            for (int nt = 0; nt < 8; nt++) {
                const int bb = (nt * 8 + g) * AT_ROWB + ks * 32 + t * 4;
                uint32_t bhf[2], blf[2];
                bhf[0] = *reinterpret_cast<const uint32_t*>(stg + bb);
                bhf[1] = *reinterpret_cast<const uint32_t*>(stg + bb + 16);
                blf[0] = *reinterpret_cast<const uint32_t*>(stg + AT_KV_BYTES + bb);
                blf[1] = *reinterpret_cast<const uint32_t*>(stg + AT_KV_BYTES + bb + 16);
                mma16816(sacc[nt], ah, bhf);
                mma16816(sacc[nt], al, bhf);
                mma16816(sacc[nt], ah, blf);
            }
        }

        const bool masked = (jt >= 2 * qt);
#pragma unroll
        for (int nt = 0; nt < 8; nt++) {
            const int col = jt * 64 + nt * 8 + 2 * t;
            sacc[nt][0] *= 0.125f; sacc[nt][1] *= 0.125f;
            sacc[nt][2] *= 0.125f; sacc[nt][3] *= 0.125f;
            if (masked) {
                if (col     > rowa) sacc[nt][0] = -1e30f;
                if (col + 1 > rowa) sacc[nt][1] = -1e30f;
                if (col     > rowb) sacc[nt][2] = -1e30f;
                if (col + 1 > rowb) sacc[nt][3] = -1e30f;
            }
        }

        float mta = -1e30f, mtb = -1e30f;
#pragma unroll
        for (int nt = 0; nt < 8; nt++) {
            mta = fmaxf(mta, fmaxf(sacc[nt][0], sacc[nt][1]));
            mtb = fmaxf(mtb, fmaxf(sacc[nt][2], sacc[nt][3]));
        }
        mta = fmaxf(mta, __shfl_xor_sync(0xffffffffu, mta, 1));
        mta = fmaxf(mta, __shfl_xor_sync(0xffffffffu, mta, 2));
        mtb = fmaxf(mtb, __shfl_xor_sync(0xffffffffu, mtb, 1));
        mtb = fmaxf(mtb, __shfl_xor_sync(0xffffffffu, mtb, 2));

        const float mna = fmaxf(m_a, mta);
        const float mnb = fmaxf(m_b, mtb);
        const float ala = __expf(m_a - mna);
        const float alb = __expf(m_b - mnb);

        float sa = 0.f, sbm = 0.f;
#pragma unroll
        for (int nt = 0; nt < 8; nt++) {
            sacc[nt][0] = __expf(sacc[nt][0] - mna);
            sacc[nt][1] = __expf(sacc[nt][1] - mna);
            sacc[nt][2] = __expf(sacc[nt][2] - mnb);
            sacc[nt][3] = __expf(sacc[nt][3] - mnb);
            sa  += sacc[nt][0] + sacc[nt][1];
            sbm += sacc[nt][2] + sacc[nt][3];
        }
        sa  += __shfl_xor_sync(0xffffffffu, sa, 1);
        sa  += __shfl_xor_sync(0xffffffffu, sa, 2);
        sbm += __shfl_xor_sync(0xffffffffu, sbm, 1);
        sbm += __shfl_xor_sync(0xffffffffu, sbm, 2);

        l_a = l_a * ala + sa;
        l_b = l_b * alb + sbm;
        m_a = mna; m_b = mnb;

#pragma unroll
        for (int nt = 0; nt < 8; nt++) {
            oacc[nt][0] *= ala; oacc[nt][1] *= ala;
            oacc[nt][2] *= alb; oacc[nt][3] *= alb;
        }

#pragma unroll
        for (int ks = 0; ks < 4; ks++) {
            uint32_t ph[4], pl[4];
            packsplit(sacc[2 * ks][0],     sacc[2 * ks][1],     ph[0], pl[0]);
            packsplit(sacc[2 * ks][2],     sacc[2 * ks][3],     ph[1], pl[1]);
            packsplit(sacc[2 * ks + 1][0], sacc[2 * ks + 1][1], ph[2], pl[2]);
            packsplit(sacc[2 * ks + 1][2], sacc[2 * ks + 1][3], ph[3], pl[3]);
#pragma unroll
            for (int nt = 0; nt < 8; nt++) {
                const int vb = (nt * 8 + g) * AT_ROWB + ks * 32 + t * 4;
                uint32_t bvh[2], bvl[2];
                bvh[0] = *reinterpret_cast<const uint32_t*>(stg + 2 * AT_KV_BYTES + vb);
                bvh[1] = *reinterpret_cast<const uint32_t*>(stg + 2 * AT_KV_BYTES + vb + 16);
                bvl[0] = *reinterpret_cast<const uint32_t*>(stg + 3 * AT_KV_BYTES + vb);
                bvl[1] = *reinterpret_cast<const uint32_t*>(stg + 3 * AT_KV_BYTES + vb + 16);
                mma16816(oacc[nt], ph, bvh);
                mma16816(oacc[nt], pl, bvh);
                mma16816(oacc[nt], ph, bvl);
            }
        }
        __syncthreads();
    }

    const int b = bh >> 4;
    const int h = bh & 15;
    const float inva = 1.0f / l_a;
    const float invb = 1.0f / l_b;
#pragma unroll
    for (int nt = 0; nt < 8; nt++) {
        const int d = nt * 8 + 2 * t;
        uint32_t hi, lo;
        size_t ia = ((size_t)b * SS + rowa) * DD + h * 64 + d;
        size_t ib = ((size_t)b * SS + rowb) * DD + h * 64 + d;
        packsplit(oacc[nt][0] * inva, oacc[nt][1] * inva, hi, lo);
        *reinterpret_cast<uint32_t*>(Oh + ia) = hi;
        *reinterpret_cast<uint32_t*>(Ol + ia) = lo;
        packsplit(oacc[nt][2] * invb, oacc[nt][3] * invb, hi, lo);
        *reinterpret_cast<uint32_t*>(Oh + ib) = hi;
        *reinterpret_cast<uint32_t*>(Ol + ib) = lo;
    }
}

// ---------------------------------------------------------------------------
// Host launch
// ---------------------------------------------------------------------------
extern "C" void kernel_launch(void* const* d_in, const int* in_sizes, int n_in,
                              void* d_out, int out_size)
{
    const float* hidden   = (const float*)d_in[0];
    const float* q_U      = (const float*)d_in[1];
    const float* q_V      = (const float*)d_in[2];
    const float* q_bias   = (const float*)d_in[3];
    const float* k_U      = (const float*)d_in[4];
    const float* k_V      = (const float*)d_in[5];
    const float* k_bias   = (const float*)d_in[6];
    const float* v_U      = (const float*)d_in[7];
    const float* v_V      = (const float*)d_in[8];
    const float* v_bias   = (const float*)d_in[9];
    const float* out_U    = (const float*)d_in[10];
    const float* out_V    = (const float*)d_in[11];
    const float* out_bias = (const float*)d_in[12];
    const float* fc1_U    = (const float*)d_in[13];
    const float* fc1_V    = (const float*)d_in[14];
    const float* fc1_bias = (const float*)d_in[15];
    const float* fc2_U    = (const float*)d_in[16];
    const float* fc2_V    = (const float*)d_in[17];
    const float* fc2_bias = (const float*)d_in[18];
    const float* ln1_w    = (const float*)d_in[19];
    const float* ln1_b    = (const float*)d_in[20];
    const float* ln2_w    = (const float*)d_in[21];
    const float* ln2_b    = (const float*)d_in[22];
    float* out = (float*)d_out;

    float *p_Tq, *p_Tk, *p_Tv, *p_h;
    bf16 *p_normh, *p_norml, *p_qh, *p_ql, *p_kh, *p_kl, *p_vth, *p_vtl;
    bf16 *p_attnh, *p_attnl, *p_tmph, *p_tmpl, *p_ffh, *p_ffl, *p_wh, *p_wl;
    cudaGetSymbolAddress((void**)&p_normh, g_normh);
    cudaGetSymbolAddress((void**)&p_norml, g_norml);
    cudaGetSymbolAddress((void**)&p_Tq, g_Tq);
    cudaGetSymbolAddress((void**)&p_Tk, g_Tk);
    cudaGetSymbolAddress((void**)&p_Tv, g_Tv);
    cudaGetSymbolAddress((void**)&p_qh, g_qh);
    cudaGetSymbolAddress((void**)&p_ql, g_ql);
    cudaGetSymbolAddress((void**)&p_kh, g_kh);
    cudaGetSymbolAddress((void**)&p_kl, g_kl);
    cudaGetSymbolAddress((void**)&p_vth, g_vth);
    cudaGetSymbolAddress((void**)&p_vtl, g_vtl);
    cudaGetSymbolAddress((void**)&p_attnh, g_attnh);
    cudaGetSymbolAddress((void**)&p_attnl, g_attnl);
    cudaGetSymbolAddress((void**)&p_tmph, g_tmph);
    cudaGetSymbolAddress((void**)&p_tmpl, g_tmpl);
    cudaGetSymbolAddress((void**)&p_ffh, g_ffh);
    cudaGetSymbolAddress((void**)&p_ffl, g_ffl);
    cudaGetSymbolAddress((void**)&p_h, g_h);
    cudaGetSymbolAddress((void**)&p_wh, g_wh);
    cudaGetSymbolAddress((void**)&p_wl, g_wl);

    cudaFuncSetAttribute(attn_mma_kernel, cudaFuncAttributeMaxDynamicSharedMemorySize, AT_SMEM);
    cudaFuncSetAttribute(bgemm<0,0>, cudaFuncAttributeMaxDynamicSharedMemorySize, BG_SMEM);
    cudaFuncSetAttribute(bgemm<1,0>, cudaFuncAttributeMaxDynamicSharedMemorySize, BG_SMEM);
    cudaFuncSetAttribute(bgemm<1,1>, cudaFuncAttributeMaxDynamicSharedMemorySize, BG_SMEM);
    cudaFuncSetAttribute(bgemm<0,2>, cudaFuncAttributeMaxDynamicSharedMemorySize, BG_SMEM);

    // 0. split weights
    {
        struct { const float* src; int off; int n; } ws[9] = {
            {q_V,   WOFF_QV,  RA * HH * DD}, {k_V, WOFF_KV, RA * HH * DD},
            {v_V,   WOFF_VV,  RA * HH * DD},
            {out_V, WOFF_OV,  RO * DD}, {out_U, WOFF_OU, DD * RO},
            {fc1_V, WOFF_F1V, RF * DD}, {fc1_U, WOFF_F1U, INTER * RF},
            {fc2_V, WOFF_F2V, RF * INTER}, {fc2_U, WOFF_F2U, DD * RF},
        };
        for (int i = 0; i < 9; i++) {
            int n8 = ws[i].n / 8;
            wsplit_kernel<<<(n8 + 255) / 256, 256>>>(ws[i].src, p_wh + ws[i].off,
                                                     p_wl + ws[i].off, n8);
        }
    }

    // 1. LN1 -> bf16 hi/lo
    ln_kernel<<<BS, 256>>>(hidden, ln1_w, ln1_b, p_normh, p_norml);

    // 2. rank projections (fp32 out)
    {
        dim3 g(512 / 128, BS / 128);
        bgemm<0,0><<<g, 256, BG_SMEM>>>(BS, 512, DD, p_normh, p_norml,
            p_wh + WOFF_QV, p_wl + WOFF_QV, nullptr, nullptr, p_Tq, nullptr, nullptr);
        bgemm<0,0><<<g, 256, BG_SMEM>>>(BS, 512, DD, p_normh, p_norml,
            p_wh + WOFF_KV, p_wl + WOFF_KV, nullptr, nullptr, p_Tk, nullptr, nullptr);
        bgemm<0,0><<<g, 256, BG_SMEM>>>(BS, 512, DD, p_normh, p_norml,
            p_wh + WOFF_VV, p_wl + WOFF_VV, nullptr, nullptr, p_Tv, nullptr, nullptr);
    }

    // 3. U projection -> bf16 hi/lo q,k (row) and v (transposed)
    {
        dim3 g(BS / 64, HH);
        uproj_kernel<0><<<g, 256>>>(p_Tq, q_U, q_bias, p_qh, p_ql);
        uproj_kernel<0><<<g, 256>>>(p_Tk, k_U, k_bias, p_kh, p_kl);
        uproj_kernel<1><<<g, 256>>>(p_Tv, v_U, v_bias, p_vth, p_vtl);
    }

    // 4. causal attention -> bf16 hi/lo [B,S,D]
    {
        dim3 g(SS / 128, BB * HH);
        attn_mma_kernel<<<g, 256, AT_SMEM>>>(p_qh, p_ql, p_kh, p_kl, p_vth, p_vtl,
                                             p_attnh, p_attnl);
    }

    // 5-6. out projection + residual
    {
        dim3 g1(RO / 128, BS / 128);
        bgemm<1,0><<<g1, 256, BG_SMEM>>>(BS, RO, DD, p_attnh, p_attnl,
            p_wh + WOFF_OV, p_wl + WOFF_OV, nullptr, nullptr, nullptr, p_tmph, p_tmpl);
        dim3 g2(DD / 128, BS / 128);
        bgemm<0,2><<<g2, 256, BG_SMEM>>>(BS, DD, RO, p_tmph, p_tmpl,
            p_wh + WOFF_OU, p_wl + WOFF_OU, out_bias, hidden, p_h, nullptr, nullptr);
    }

    // 7. LN2 -> bf16 hi/lo
    ln_kernel<<<BS, 256>>>(p_h, ln2_w, ln2_b, p_normh, p_norml);

    // 8-9. FC1 + bias + exact GELU
    {
        dim3 g1(RF / 128, BS / 128);
        bgemm<1,0><<<g1, 256, BG_SMEM>>>(BS, RF, DD, p_normh, p_norml,
            p_wh + WOFF_F1V, p_wl + WOFF_F1V, nullptr, nullptr, nullptr, p_tmph, p_tmpl);
        dim3 g2(INTER / 128, BS / 128);
        bgemm<1,1><<<g2, 256, BG_SMEM>>>(BS, INTER, RF, p_tmph, p_tmpl,
            p_wh + WOFF_F1U, p_wl + WOFF_F1U, fc1_bias, nullptr, nullptr, p_ffh, p_ffl);
    }

    // 10-11. FC2 + bias + residual -> out
    {
        dim3 g1(RF / 128, BS / 128);
        bgemm<1,0><<<g1, 256, BG_SMEM>>>(BS, RF, INTER, p_ffh, p_ffl,
            p_wh + WOFF_F2V, p_wl + WOFF_F2V, nullptr, nullptr, nullptr, p_tmph, p_tmpl);
        dim3 g2(DD / 128, BS / 128);
        bgemm<0,2><<<g2, 256, BG_SMEM>>>(BS, DD, RF, p_tmph, p_tmpl,
            p_wh + WOFF_F2U, p_wl + WOFF_F2U, fc2_bias, p_h, out, nullptr, nullptr);
    }
    (void)in_sizes; (void)n_in; (void)out_size;
}

// round 6
// speedup vs baseline: 1.1196x; 1.1196x over previous
#include <cuda_runtime.h>
#include <cuda_bf16.h>
#include <math.h>
#include <stdint.h>

// Problem constants
#define BB 2
#define SS 2048
#define DD 1024
#define HH 16
#define HD 64
#define RA 32
#define RF 512
#define RO 512
#define INTER 4096
#define BS (BB * SS)          // 4096 rows
#define CLAMP_V 1.0e6f
#define LN_EPS 1e-5f

typedef __nv_bfloat16 bf16;

// ---------------------------------------------------------------------------
// Scratch (device globals: allocation-free)
// ---------------------------------------------------------------------------
__device__ __align__(256) bf16 g_normh[BS * DD];
__device__ __align__(256) bf16 g_norml[BS * DD];
__device__ __align__(256) float g_Tq[BS * (HH * RA)];
__device__ __align__(256) float g_Tk[BS * (HH * RA)];
__device__ __align__(256) float g_Tv[BS * (HH * RA)];
__device__ __align__(256) bf16 g_qh[BB * HH * SS * HD];
__device__ __align__(256) bf16 g_ql[BB * HH * SS * HD];
__device__ __align__(256) bf16 g_kh[BB * HH * SS * HD];
__device__ __align__(256) bf16 g_kl[BB * HH * SS * HD];
__device__ __align__(256) bf16 g_vth[BB * HH * HD * SS];
__device__ __align__(256) bf16 g_vtl[BB * HH * HD * SS];
__device__ __align__(256) bf16 g_attnh[BS * DD];
__device__ __align__(256) bf16 g_attnl[BS * DD];
__device__ __align__(256) bf16 g_tmph[BS * 512];
__device__ __align__(256) bf16 g_tmpl[BS * 512];
__device__ __align__(256) bf16 g_ffh[BS * INTER];
__device__ __align__(256) bf16 g_ffl[BS * INTER];
__device__ __align__(256) float g_h[BS * DD];
// split-weight pool (7,864,320 elems)
#define WOFF_QV   0
#define WOFF_KV   524288
#define WOFF_VV   1048576
#define WOFF_OV   1572864
#define WOFF_OU   2097152
#define WOFF_F1V  2621440
#define WOFF_F1U  3145728
#define WOFF_F2V  5242880
#define WOFF_F2U  7340032
#define WPOOL_SZ  7864320
__device__ __align__(256) bf16 g_wh[WPOOL_SZ];
__device__ __align__(256) bf16 g_wl[WPOOL_SZ];

// ---------------------------------------------------------------------------
// helpers
// ---------------------------------------------------------------------------
__device__ __forceinline__ void mma16816(float* c, const uint32_t* a, const uint32_t* b) {
    asm volatile(
        "mma.sync.aligned.m16n8k16.row.col.f32.bf16.bf16.f32 "
        "{%0,%1,%2,%3}, {%4,%5,%6,%7}, {%8,%9}, {%0,%1,%2,%3};"
        : "+f"(c[0]), "+f"(c[1]), "+f"(c[2]), "+f"(c[3])
        : "r"(a[0]), "r"(a[1]), "r"(a[2]), "r"(a[3]), "r"(b[0]), "r"(b[1]));
}
__device__ __forceinline__ void packsplit(float f0, float f1, uint32_t& hi, uint32_t& lo) {
    __nv_bfloat162 h = __floats2bfloat162_rn(f0, f1);
    hi = *reinterpret_cast<uint32_t*>(&h);
    __nv_bfloat162 l = __floats2bfloat162_rn(f0 - __bfloat162float(h.x),
                                             f1 - __bfloat162float(h.y));
    lo = *reinterpret_cast<uint32_t*>(&l);
}
__device__ __forceinline__ void split8(const float4& f0, const float4& f1,
                                       uint4& hi, uint4& lo) {
    float f[8] = {f0.x, f0.y, f0.z, f0.w, f1.x, f1.y, f1.z, f1.w};
    uint32_t h[4], l[4];
#pragma unroll
    for (int j = 0; j < 4; j++) packsplit(f[2 * j], f[2 * j + 1], h[j], l[j]);
    hi = make_uint4(h[0], h[1], h[2], h[3]);
    lo = make_uint4(l[0], l[1], l[2], l[3]);
}
#define CP_ASYNC16(dst, src) \
    asm volatile("cp.async.cg.shared.global [%0], [%1], 16;" :: "r"(dst), "l"(src) : "memory")
#define CP_COMMIT() asm volatile("cp.async.commit_group;" ::: "memory")
#define CP_WAIT0() asm volatile("cp.async.wait_group 0;" ::: "memory")
#define CP_WAIT1() asm volatile("cp.async.wait_group 1;" ::: "memory")
#define CP_WAIT2() asm volatile("cp.async.wait_group 2;" ::: "memory")
#define LDSM4(r, addr) \
    asm volatile("ldmatrix.sync.aligned.m8n8.x4.shared.b16 {%0,%1,%2,%3}, [%4];" \
        : "=r"((r)[0]), "=r"((r)[1]), "=r"((r)[2]), "=r"((r)[3]) : "r"(addr))
#define LDSM2(r, addr) \
    asm volatile("ldmatrix.sync.aligned.m8n8.x2.shared.b16 {%0,%1}, [%2];" \
        : "=r"((r)[0]), "=r"((r)[1]) : "r"(addr))
__device__ __forceinline__ uint32_t smem_u32(const void* p) {
    uint32_t a;
    asm("{ .reg .u64 t; cvta.to.shared.u64 t, %1; cvt.u32.u64 %0, t; }" : "=r"(a) : "l"(p));
    return a;
}

// ---------------------------------------------------------------------------
// fused weight split: one launch, 9 segments; pool index == global index
// ---------------------------------------------------------------------------
struct WSrcs { const float* p[9]; };
__global__ __launch_bounds__(256) void wsplit_all(
    WSrcs srcs, bf16* __restrict__ hi, bf16* __restrict__ lo)
{
    const int i = blockIdx.x * 256 + threadIdx.x;   // < 983040
    const int bnd[9] = {65536, 131072, 196608, 262144, 327680,
                        393216, 655360, 917504, 983040};
    int s = 0;
#pragma unroll
    for (int j = 0; j < 8; j++)
        if (i >= bnd[j]) s = j + 1;
    const int base = s ? bnd[s - 1] : 0;
    const float* src = srcs.p[s] + (size_t)(i - base) * 8;
    float4 f0 = *reinterpret_cast<const float4*>(src);
    float4 f1 = *reinterpret_cast<const float4*>(src + 4);
    uint4 h, l;
    split8(f0, f1, h, l);
    *reinterpret_cast<uint4*>(hi + (size_t)i * 8) = h;
    *reinterpret_cast<uint4*>(lo + (size_t)i * 8) = l;
}

// ---------------------------------------------------------------------------
// bgemm2: C[M,N] = A[M,K] @ W[N,K]^T, 3-term bf16 split.
// 64x128 tile, 256 threads, 8 warps (2Mx4N), warp tile 32x32.
// Unpadded XOR-swizzled smem (chunk ^= (row>>1)&3), 3-stage cp.async.
// __launch_bounds__(256, 2) -> target 2 CTAs/SM (16 warps).
// OUTBF16: write bf16 hi/lo else fp32. EPI: 0 bias; 1 bias+GELU; 2 bias+res.
// ---------------------------------------------------------------------------
#define B2_AL    4096
#define B2_BH    8192
#define B2_BL    16384
#define B2_STAGE 24576
#define B2_SMEM  (3 * B2_STAGE)    // 73728

__device__ __forceinline__ uint32_t b2_sw(int row, int c) {
    return (uint32_t)(row * 64 + ((c ^ ((row >> 1) & 3)) << 4));
}

__device__ __forceinline__ void b2_load(
    uint32_t stg, const bf16* Ah, const bf16* Al, const bf16* Bh, const bf16* Bl,
    int K, int k0, int tid)
{
#pragma unroll
    for (int i = 0; i < 6; i++) {
        int idx = tid + 256 * i;          // 1536 chunks of 16B
        const bf16* src;
        uint32_t dst;
        if (idx < 512) {
            int a = idx >> 8;             // 0: Ah, 1: Al
            int rem = idx & 255;
            int row = rem >> 2, c = rem & 3;
            dst = stg + (a ? B2_AL : 0u) + b2_sw(row, c);
            src = (a ? Al : Ah) + (size_t)row * K + k0 + c * 8;
        } else {
            int rem = idx - 512;
            int a = rem >> 9;             // 0: Bh, 1: Bl
            rem &= 511;
            int row = rem >> 2, c = rem & 3;
            dst = stg + (a ? B2_BL : B2_BH) + b2_sw(row, c);
            src = (a ? Bl : Bh) + (size_t)row * K + k0 + c * 8;
        }
        CP_ASYNC16(dst, src);
    }
}

template <int OUTBF16, int EPI>
__global__ __launch_bounds__(256, 2) void bgemm2(
    int M, int N, int K,
    const bf16* __restrict__ Ah, const bf16* __restrict__ Al,
    const bf16* __restrict__ Wh, const bf16* __restrict__ Wl,
    const float* __restrict__ bias, const float* __restrict__ res,
    float* __restrict__ C, bf16* __restrict__ Ch, bf16* __restrict__ Cl)
{
    extern __shared__ char sm[];
    const uint32_t sb = smem_u32(sm);
    const int tid = threadIdx.x;
    const int lane = tid & 31;
    const int warp = tid >> 5;
    const int wm = (warp >> 2) * 32;     // 0 / 32
    const int wn = (warp & 3) * 32;      // 0..96
    const int bm = blockIdx.y * 64;
    const int bn = blockIdx.x * 128;

    const bf16* Ab  = Ah + (size_t)bm * K;
    const bf16* Alb = Al + (size_t)bm * K;
    const bf16* Wb  = Wh + (size_t)bn * K;
    const bf16* Wlb = Wl + (size_t)bn * K;
    const int nchunks = K >> 5;

    float acc[2][4][4];
#pragma unroll
    for (int i = 0; i < 2; i++)
#pragma unroll
        for (int j = 0; j < 4; j++)
#pragma unroll
            for (int k = 0; k < 4; k++) acc[i][j][k] = 0.f;

#pragma unroll
    for (int s = 0; s < 3; s++) {
        b2_load(sb + s * B2_STAGE, Ab, Alb, Wb, Wlb, K, s << 5, tid);
        CP_COMMIT();
    }

    // fragment lane geometry
    const int aRow = wm + (lane & 15);            // swizzle mask invariant over mt*16
    const int sA = (aRow >> 1) & 3;
    const int bRow = wn + (lane & 7);             // invariant over nt*8
    const int sB = (bRow >> 1) & 3;
    const int kcA = lane >> 4;                    // 0/1
    const int kcB = (lane >> 3) & 1;

    int slot = 0;
    for (int c = 0; c < nchunks; c++) {
        CP_WAIT2();
        __syncthreads();
        const uint32_t stg = sb + (uint32_t)slot * B2_STAGE;

#pragma unroll
        for (int kk = 0; kk < 2; kk++) {
            uint32_t ah[2][4], al[2][4], bh[4][2], bl[4][2];
#pragma unroll
            for (int mt = 0; mt < 2; mt++) {
                uint32_t ad = stg + (uint32_t)((aRow + mt * 16) * 64) +
                              (uint32_t)(((kk * 2 + kcA) ^ sA) << 4);
                LDSM4(ah[mt], ad);
                LDSM4(al[mt], ad + B2_AL);
            }
#pragma unroll
            for (int nt = 0; nt < 4; nt++) {
                uint32_t bd = stg + B2_BH + (uint32_t)((bRow + nt * 8) * 64) +
                              (uint32_t)(((kk * 2 + kcB) ^ sB) << 4);
                LDSM2(bh[nt], bd);
                LDSM2(bl[nt], bd + (B2_BL - B2_BH));
            }
#pragma unroll
            for (int mt = 0; mt < 2; mt++)
#pragma unroll
                for (int nt = 0; nt < 4; nt++)
                    mma16816(acc[mt][nt], ah[mt], bh[nt]);
#pragma unroll
            for (int mt = 0; mt < 2; mt++)
#pragma unroll
                for (int nt = 0; nt < 4; nt++)
                    mma16816(acc[mt][nt], al[mt], bh[nt]);
#pragma unroll
            for (int mt = 0; mt < 2; mt++)
#pragma unroll
                for (int nt = 0; nt < 4; nt++)
                    mma16816(acc[mt][nt], ah[mt], bl[nt]);
        }
        __syncthreads();
        if (c + 3 < nchunks)
            b2_load(sb + (uint32_t)slot * B2_STAGE, Ab, Alb, Wb, Wlb, K, (c + 3) << 5, tid);
        CP_COMMIT();
        slot = (slot == 2) ? 0 : slot + 1;
    }

    // epilogue
#pragma unroll
    for (int mt = 0; mt < 2; mt++) {
#pragma unroll
        for (int nt = 0; nt < 4; nt++) {
            const float* cc = acc[mt][nt];
            const int gr = bm + wm + mt * 16 + (lane >> 2);
            const int gc = bn + wn + nt * 8 + (lane & 3) * 2;
            float b0 = 0.f, b1 = 0.f;
            if (bias) { b0 = bias[gc]; b1 = bias[gc + 1]; }
#pragma unroll
            for (int half = 0; half < 2; half++) {
                const int row = gr + half * 8;
                float v0 = cc[half * 2 + 0] + b0;
                float v1 = cc[half * 2 + 1] + b1;
                if (EPI == 1) {
                    v0 = 0.5f * v0 * (1.0f + erff(v0 * 0.70710678118654752f));
                    v1 = 0.5f * v1 * (1.0f + erff(v1 * 0.70710678118654752f));
                }
                if (EPI == 2) {
                    float2 r2 = *reinterpret_cast<const float2*>(res + (size_t)row * N + gc);
                    v0 += r2.x; v1 += r2.y;
                }
                if (OUTBF16) {
                    uint32_t hi, lo;
                    packsplit(v0, v1, hi, lo);
                    *reinterpret_cast<uint32_t*>(Ch + (size_t)row * N + gc) = hi;
                    *reinterpret_cast<uint32_t*>(Cl + (size_t)row * N + gc) = lo;
                } else {
                    *reinterpret_cast<float2*>(C + (size_t)row * N + gc) = make_float2(v0, v1);
                }
            }
        }
    }
}

// ---------------------------------------------------------------------------
// LayerNorm -> bf16 hi/lo output
// ---------------------------------------------------------------------------
__global__ __launch_bounds__(256) void ln_kernel(
    const float* __restrict__ x, const float* __restrict__ w,
    const float* __restrict__ b, bf16* __restrict__ oh, bf16* __restrict__ ol)
{
    __shared__ float warpred[8];
    __shared__ float s_mean, s_var;
    const int row = blockIdx.x;
    const int tid = threadIdx.x;
    const float* xr = x + (size_t)row * DD;

    float4 v = *reinterpret_cast<const float4*>(xr + tid * 4);
    float local = v.x + v.y + v.z + v.w;
#pragma unroll
    for (int off = 16; off > 0; off >>= 1)
        local += __shfl_xor_sync(0xffffffffu, local, off);
    if ((tid & 31) == 0) warpred[tid >> 5] = local;
    __syncthreads();
    if (tid == 0) {
        float s = 0.f;
#pragma unroll
        for (int i = 0; i < 8; i++) s += warpred[i];
        s_mean = s * (1.0f / DD);
    }
    __syncthreads();
    const float mean = s_mean;

    float d0 = v.x - mean, d1 = v.y - mean, d2 = v.z - mean, d3 = v.w - mean;
    local = d0 * d0 + d1 * d1 + d2 * d2 + d3 * d3;
#pragma unroll
    for (int off = 16; off > 0; off >>= 1)
        local += __shfl_xor_sync(0xffffffffu, local, off);
    if ((tid & 31) == 0) warpred[tid >> 5] = local;
    __syncthreads();
    if (tid == 0) {
        float s = 0.f;
#pragma unroll
        for (int i = 0; i < 8; i++) s += warpred[i];
        s_var = s * (1.0f / DD);
    }
    __syncthreads();
    const float rstd = rsqrtf(s_var + LN_EPS);

    float4 wv = *reinterpret_cast<const float4*>(w + tid * 4);
    float4 bv = *reinterpret_cast<const float4*>(b + tid * 4);
    float y0 = d0 * rstd * wv.x + bv.x;
    float y1 = d1 * rstd * wv.y + bv.y;
    float y2 = d2 * rstd * wv.z + bv.z;
    float y3 = d3 * rstd * wv.w + bv.w;
    uint32_t h0, l0, h1, l1;
    packsplit(y0, y1, h0, l0);
    packsplit(y2, y3, h1, l1);
    size_t base = (size_t)row * DD + tid * 4;
    *reinterpret_cast<uint32_t*>(oh + base) = h0;
    *reinterpret_cast<uint32_t*>(oh + base + 2) = h1;
    *reinterpret_cast<uint32_t*>(ol + base) = l0;
    *reinterpret_cast<uint32_t*>(ol + base + 2) = l1;
}

// ---------------------------------------------------------------------------
// Per-head U projection -> bf16 hi/lo. TRANS=0: [B,H,S,HD]; 1: [B,H,HD,S]
// ---------------------------------------------------------------------------
template <int TRANS>
__global__ __launch_bounds__(256) void uproj_kernel(
    const float* __restrict__ T, const float* __restrict__ U,
    const float* __restrict__ bias,
    bf16* __restrict__ oh, bf16* __restrict__ ol)
{
    __shared__ float Us[HD][RA + 1];
    __shared__ float Ts[64][RA + 1];
    const int head = blockIdx.y;
    const int s0 = blockIdx.x * 64;
    const int tid = threadIdx.x;

#pragma unroll
    for (int i = 0; i < 8; i++) {
        int idx = tid + 256 * i;
        Us[idx >> 5][idx & 31] = U[(size_t)head * (HD * RA) + idx];
    }
#pragma unroll
    for (int i = 0; i < 8; i++) {
        int idx = tid + 256 * i;
        int sl = idx >> 5, r = idx & 31;
        Ts[sl][r] = T[(size_t)(s0 + sl) * (HH * RA) + head * RA + r];
    }
    __syncthreads();

    const int sl = tid >> 2;
    const int eg = tid & 3;
    float accv[16];
#pragma unroll
    for (int i = 0; i < 16; i++) accv[i] = 0.f;
#pragma unroll
    for (int r = 0; r < RA; r++) {
        float t = Ts[sl][r];
#pragma unroll
        for (int i = 0; i < 16; i++)
            accv[i] += t * Us[eg + 4 * i][r];
    }

    const int bs = s0 + sl;
    const int bb = bs / SS;
    const int s = bs - bb * SS;
#pragma unroll
    for (int i = 0; i < 16; i++) {
        int e = eg + 4 * i;
        float v = accv[i] + bias[head * HD + e];
        v = fminf(fmaxf(v, -CLAMP_V), CLAMP_V);
        bf16 hh = __float2bfloat16(v);
        bf16 ll = __float2bfloat16(v - __bfloat162float(hh));
        size_t idx;
        if (TRANS)
            idx = ((size_t)(bb * HH + head) * HD + e) * SS + s;
        else
            idx = ((size_t)(bb * HH + head) * SS + s) * HD + e;
        oh[idx] = hh;
        ol[idx] = ll;
    }
}

// ---------------------------------------------------------------------------
// Flash attention (mma.sync bf16, 3-term splits), epilogue -> bf16 hi/lo
// ---------------------------------------------------------------------------
#define AT_ROWB 144
#define AT_Q_BYTES (128 * AT_ROWB)
#define AT_KV_BYTES (64 * AT_ROWB)
#define AT_STG_BYTES (4 * AT_KV_BYTES)
#define AT_STG0 (2 * AT_Q_BYTES)
#define AT_SMEM (AT_STG0 + 2 * AT_STG_BYTES)

__device__ __forceinline__ void attn_load_kv(
    uint32_t stg_sb, const bf16* kh, const bf16* kl,
    const bf16* vth, const bf16* vtl, int bh, int jt, int tid)
{
#pragma unroll
    for (int i = 0; i < 8; i++) {
        int idx = tid + 256 * i;
        int a = idx >> 9;
        int rem = idx & 511;
        int row = rem >> 3;
        int c = rem & 7;
        uint32_t dst = stg_sb + (uint32_t)a * AT_KV_BYTES + row * AT_ROWB + c * 16;
        const bf16* src;
        if (a == 0)      src = kh  + ((size_t)bh * SS + jt * 64 + row) * HD + c * 8;
        else if (a == 1) src = kl  + ((size_t)bh * SS + jt * 64 + row) * HD + c * 8;
        else if (a == 2) src = vth + ((size_t)bh * HD + row) * SS + jt * 64 + c * 8;
        else             src = vtl + ((size_t)bh * HD + row) * SS + jt * 64 + c * 8;
        CP_ASYNC16(dst, src);
    }
}

__global__ __launch_bounds__(256) void attn_mma_kernel(
    const bf16* __restrict__ qh, const bf16* __restrict__ ql,
    const bf16* __restrict__ kh, const bf16* __restrict__ kl,
    const bf16* __restrict__ vth, const bf16* __restrict__ vtl,
    bf16* __restrict__ Oh, bf16* __restrict__ Ol)
{
    extern __shared__ char asmm[];
    const uint32_t sb = smem_u32(asmm);
    const int bh = blockIdx.y;
    const int qt = blockIdx.x;
    const int tid = threadIdx.x;
    const int lane = tid & 31;
    const int warp = tid >> 5;
    const int g = lane >> 2;
    const int t = lane & 3;
    const int wm = warp * 16;

#pragma unroll
    for (int i = 0; i < 8; i++) {
        int idx = tid + 256 * i;
        int a = idx >> 10;
        int rem = idx & 1023;
        int row = rem >> 3;
        int c = rem & 7;
        uint32_t dst = sb + (uint32_t)a * AT_Q_BYTES + row * AT_ROWB + c * 16;
        const bf16* src = (a ? ql : qh) + ((size_t)bh * SS + qt * 128 + row) * HD + c * 8;
        CP_ASYNC16(dst, src);
    }
    attn_load_kv(sb + AT_STG0, kh, kl, vth, vtl, bh, 0, tid);
    CP_COMMIT();

    float m_a = -1e30f, m_b = -1e30f, l_a = 0.f, l_b = 0.f;
    float oacc[8][4];
#pragma unroll
    for (int i = 0; i < 8; i++)
#pragma unroll
        for (int j = 0; j < 4; j++) oacc[i][j] = 0.f;

    const int ntiles = 2 * qt + 2;
    const int rowa = qt * 128 + wm + g;
    const int rowb = rowa + 8;

    for (int jt = 0; jt < ntiles; jt++) {
        if (jt + 1 < ntiles) {
            attn_load_kv(sb + AT_STG0 + ((jt + 1) & 1) * AT_STG_BYTES,
                         kh, kl, vth, vtl, bh, jt + 1, tid);
            CP_COMMIT();
            CP_WAIT1();
        } else {
            CP_WAIT0();
        }
        __syncthreads();

        const char* stg = asmm + AT_STG0 + (jt & 1) * AT_STG_BYTES;
        const char* qhB = asmm;
        const char* qlB = asmm + AT_Q_BYTES;

        float sacc[8][4];
#pragma unroll
        for (int i = 0; i < 8; i++)
#pragma unroll
            for (int j = 0; j < 4; j++) sacc[i][j] = 0.f;

#pragma unroll
        for (int ks = 0; ks < 4; ks++) {
            const int ab = (wm + g) * AT_ROWB + ks * 32 + t * 4;
            uint32_t ah[4], al[4];
            ah[0] = *reinterpret_cast<const uint32_t*>(qhB + ab);
            ah[1] = *reinterpret_cast<const uint32_t*>(qhB + ab + 8 * AT_ROWB);
            ah[2] = *reinterpret_cast<const uint32_t*>(qhB + ab + 16);
            ah[3] = *reinterpret_cast<const uint32_t*>(qhB + ab + 8 * AT_ROWB + 16);
            al[0] = *reinterpret_cast<const uint32_t*>(qlB + ab);
            al[1] = *reinterpret_cast<const uint32_t*>(qlB + ab + 8 * AT_ROWB);
            al[2] = *reinterpret_cast<const uint32_t*>(qlB + ab + 16);
            al[3] = *reinterpret_cast<const uint32_t*>(qlB + ab + 8 * AT_ROWB + 16);
#pragma unroll
            for (int nt = 0; nt < 8; nt++) {
                const int bb = (nt * 8 + g) * AT_ROWB + ks * 32 + t * 4;
                uint32_t bhf[2], blf[2];
                bhf[0] = *reinterpret_cast<const uint32_t*>(stg + bb);
                bhf[1] = *reinterpret_cast<const uint32_t*>(stg + bb + 16);
                blf[0] = *reinterpret_cast<const uint32_t*>(stg + AT_KV_BYTES + bb);
                blf[1] = *reinterpret_cast<const uint32_t*>(stg + AT_KV_BYTES + bb + 16);
                mma16816(sacc[nt], ah, bhf);
                mma16816(sacc[nt], al, bhf);
                mma16816(sacc[nt], ah, blf);
            }
        }

        const bool masked = (jt >= 2 * qt);
#pragma unroll
        for (int nt = 0; nt < 8; nt++) {
            const int col = jt * 64 + nt * 8 + 2 * t;
            sacc[nt][0] *= 0.125f; sacc[nt][1] *= 0.125f;
            sacc[nt][2] *= 0.125f; sacc[nt][3] *= 0.125f;
            if (masked) {
                if (col     > rowa) sacc[nt][0] = -1e30f;
                if (col + 1 > rowa) sacc[nt][1] = -1e30f;
                if (col     > rowb) sacc[nt][2] = -1e30f;
                if (col + 1 > rowb) sacc[nt][3] = -1e30f;
            }
        }

        float mta = -1e30f, mtb = -1e30f;
#pragma unroll
        for (int nt = 0; nt < 8; nt++) {
            mta = fmaxf(mta, fmaxf(sacc[nt][0], sacc[nt][1]));
            mtb = fmaxf(mtb, fmaxf(sacc[nt][2], sacc[nt][3]));
        }
        mta = fmaxf(mta, __shfl_xor_sync(0xffffffffu, mta, 1));
        mta = fmaxf(mta, __shfl_xor_sync(0xffffffffu, mta, 2));
        mtb = fmaxf(mtb, __shfl_xor_sync(0xffffffffu, mtb, 1));
        mtb = fmaxf(mtb, __shfl_xor_sync(0xffffffffu, mtb, 2));

        const float mna = fmaxf(m_a, mta);
        const float mnb = fmaxf(m_b, mtb);
        const float ala = __expf(m_a - mna);
        const float alb = __expf(m_b - mnb);

        float sa = 0.f, sbm = 0.f;
#pragma unroll
        for (int nt = 0; nt < 8; nt++) {
            sacc[nt][0] = __expf(sacc[nt][0] - mna);
            sacc[nt][1] = __expf(sacc[nt][1] - mna);
            sacc[nt][2] = __expf(sacc[nt][2] - mnb);
            sacc[nt][3] = __expf(sacc[nt][3] - mnb);
            sa  += sacc[nt][0] + sacc[nt][1];
            sbm += sacc[nt][2] + sacc[nt][3];
        }
        sa  += __shfl_xor_sync(0xffffffffu, sa, 1);
        sa  += __shfl_xor_sync(0xffffffffu, sa, 2);
        sbm += __shfl_xor_sync(0xffffffffu, sbm, 1);
        sbm += __shfl_xor_sync(0xffffffffu, sbm, 2);

        l_a = l_a * ala + sa;
        l_b = l_b * alb + sbm;
        m_a = mna; m_b = mnb;

#pragma unroll
        for (int nt = 0; nt < 8; nt++) {
            oacc[nt][0] *= ala; oacc[nt][1] *= ala;
            oacc[nt][2] *= alb; oacc[nt][3] *= alb;
        }

#pragma unroll
        for (int ks = 0; ks < 4; ks++) {
            uint32_t ph[4], pl[4];
            packsplit(sacc[2 * ks][0],     sacc[2 * ks][1],     ph[0], pl[0]);
            packsplit(sacc[2 * ks][2],     sacc[2 * ks][3],     ph[1], pl[1]);
            packsplit(sacc[2 * ks + 1][0], sacc[2 * ks + 1][1], ph[2], pl[2]);
            packsplit(sacc[2 * ks + 1][2], sacc[2 * ks + 1][3], ph[3], pl[3]);
#pragma unroll
            for (int nt = 0; nt < 8; nt++) {
                const int vb = (nt * 8 + g) * AT_ROWB + ks * 32 + t * 4;
                uint32_t bvh[2], bvl[2];
                bvh[0] = *reinterpret_cast<const uint32_t*>(stg + 2 * AT_KV_BYTES + vb);
                bvh[1] = *reinterpret_cast<const uint32_t*>(stg + 2 * AT_KV_BYTES + vb + 16);
                bvl[0] = *reinterpret_cast<const uint32_t*>(stg + 3 * AT_KV_BYTES + vb);
                bvl[1] = *reinterpret_cast<const uint32_t*>(stg + 3 * AT_KV_BYTES + vb + 16);
                mma16816(oacc[nt], ph, bvh);
                mma16816(oacc[nt], pl, bvh);
                mma16816(oacc[nt], ph, bvl);
            }
        }
        __syncthreads();
    }

    const int b = bh >> 4;
    const int h = bh & 15;
    const float inva = 1.0f / l_a;
    const float invb = 1.0f / l_b;
#pragma unroll
    for (int nt = 0; nt < 8; nt++) {
        const int d = nt * 8 + 2 * t;
        uint32_t hi, lo;
        size_t ia = ((size_t)b * SS + rowa) * DD + h * 64 + d;
        size_t ib = ((size_t)b * SS + rowb) * DD + h * 64 + d;
        packsplit(oacc[nt][0] * inva, oacc[nt][1] * inva, hi, lo);
        *reinterpret_cast<uint32_t*>(Oh + ia) = hi;
        *reinterpret_cast<uint32_t*>(Ol + ia) = lo;
        packsplit(oacc[nt][2] * invb, oacc[nt][3] * invb, hi, lo);
        *reinterpret_cast<uint32_t*>(Oh + ib) = hi;
        *reinterpret_cast<uint32_t*>(Ol + ib) = lo;
    }
}

// ---------------------------------------------------------------------------
// Host launch
// ---------------------------------------------------------------------------
extern "C" void kernel_launch(void* const* d_in, const int* in_sizes, int n_in,
                              void* d_out, int out_size)
{
    const float* hidden   = (const float*)d_in[0];
    const float* q_U      = (const float*)d_in[1];
    const float* q_V      = (const float*)d_in[2];
    const float* q_bias   = (const float*)d_in[3];
    const float* k_U      = (const float*)d_in[4];
    const float* k_V      = (const float*)d_in[5];
    const float* k_bias   = (const float*)d_in[6];
    const float* v_U      = (const float*)d_in[7];
    const float* v_V      = (const float*)d_in[8];
    const float* v_bias   = (const float*)d_in[9];
    const float* out_U    = (const float*)d_in[10];
    const float* out_V    = (const float*)d_in[11];
    const float* out_bias = (const float*)d_in[12];
    const float* fc1_U    = (const float*)d_in[13];
    const float* fc1_V    = (const float*)d_in[14];
    const float* fc1_bias = (const float*)d_in[15];
    const float* fc2_U    = (const float*)d_in[16];
    const float* fc2_V    = (const float*)d_in[17];
    const float* fc2_bias = (const float*)d_in[18];
    const float* ln1_w    = (const float*)d_in[19];
    const float* ln1_b    = (const float*)d_in[20];
    const float* ln2_w    = (const float*)d_in[21];
    const float* ln2_b    = (const float*)d_in[22];
    float* out = (float*)d_out;

    float *p_Tq, *p_Tk, *p_Tv, *p_h;
    bf16 *p_normh, *p_norml, *p_qh, *p_ql, *p_kh, *p_kl, *p_vth, *p_vtl;
    bf16 *p_attnh, *p_attnl, *p_tmph, *p_tmpl, *p_ffh, *p_ffl, *p_wh, *p_wl;
    cudaGetSymbolAddress((void**)&p_normh, g_normh);
    cudaGetSymbolAddress((void**)&p_norml, g_norml);
    cudaGetSymbolAddress((void**)&p_Tq, g_Tq);
    cudaGetSymbolAddress((void**)&p_Tk, g_Tk);
    cudaGetSymbolAddress((void**)&p_Tv, g_Tv);
    cudaGetSymbolAddress((void**)&p_qh, g_qh);
    cudaGetSymbolAddress((void**)&p_ql, g_ql);
    cudaGetSymbolAddress((void**)&p_kh, g_kh);
    cudaGetSymbolAddress((void**)&p_kl, g_kl);
    cudaGetSymbolAddress((void**)&p_vth, g_vth);
    cudaGetSymbolAddress((void**)&p_vtl, g_vtl);
    cudaGetSymbolAddress((void**)&p_attnh, g_attnh);
    cudaGetSymbolAddress((void**)&p_attnl, g_attnl);
    cudaGetSymbolAddress((void**)&p_tmph, g_tmph);
    cudaGetSymbolAddress((void**)&p_tmpl, g_tmpl);
    cudaGetSymbolAddress((void**)&p_ffh, g_ffh);
    cudaGetSymbolAddress((void**)&p_ffl, g_ffl);
    cudaGetSymbolAddress((void**)&p_h, g_h);
    cudaGetSymbolAddress((void**)&p_wh, g_wh);
    cudaGetSymbolAddress((void**)&p_wl, g_wl);

    cudaFuncSetAttribute(attn_mma_kernel, cudaFuncAttributeMaxDynamicSharedMemorySize, AT_SMEM);
    cudaFuncSetAttribute(bgemm2<0,0>, cudaFuncAttributeMaxDynamicSharedMemorySize, B2_SMEM);
    cudaFuncSetAttribute(bgemm2<1,0>, cudaFuncAttributeMaxDynamicSharedMemorySize, B2_SMEM);
    cudaFuncSetAttribute(bgemm2<1,1>, cudaFuncAttributeMaxDynamicSharedMemorySize, B2_SMEM);
    cudaFuncSetAttribute(bgemm2<0,2>, cudaFuncAttributeMaxDynamicSharedMemorySize, B2_SMEM);

    // 0. split all weights in one launch
    {
        WSrcs ws;
        ws.p[0] = q_V;   ws.p[1] = k_V;   ws.p[2] = v_V;
        ws.p[3] = out_V; ws.p[4] = out_U;
        ws.p[5] = fc1_V; ws.p[6] = fc1_U;
        ws.p[7] = fc2_V; ws.p[8] = fc2_U;
        wsplit_all<<<3840, 256>>>(ws, p_wh, p_wl);
    }

    // 1. LN1 -> bf16 hi/lo
    ln_kernel<<<BS, 256>>>(hidden, ln1_w, ln1_b, p_normh, p_norml);

    // 2. rank projections (fp32 out)
    {
        dim3 g(512 / 128, BS / 64);
        bgemm2<0,0><<<g, 256, B2_SMEM>>>(BS, 512, DD, p_normh, p_norml,
            p_wh + WOFF_QV, p_wl + WOFF_QV, nullptr, nullptr, p_Tq, nullptr, nullptr);
        bgemm2<0,0><<<g, 256, B2_SMEM>>>(BS, 512, DD, p_normh, p_norml,
            p_wh + WOFF_KV, p_wl + WOFF_KV, nullptr, nullptr, p_Tk, nullptr, nullptr);
        bgemm2<0,0><<<g, 256, B2_SMEM>>>(BS, 512, DD, p_normh, p_norml,
            p_wh + WOFF_VV, p_wl + WOFF_VV, nullptr, nullptr, p_Tv, nullptr, nullptr);
    }

    // 3. U projection -> bf16 hi/lo q,k (row) and v (transposed)
    {
        dim3 g(BS / 64, HH);
        uproj_kernel<0><<<g, 256>>>(p_Tq, q_U, q_bias, p_qh, p_ql);
        uproj_kernel<0><<<g, 256>>>(p_Tk, k_U, k_bias, p_kh, p_kl);
        uproj_kernel<1><<<g, 256>>>(p_Tv, v_U, v_bias, p_vth, p_vtl);
    }

    // 4. causal attention -> bf16 hi/lo [B,S,D]
    {
        dim3 g(SS / 128, BB * HH);
        attn_mma_kernel<<<g, 256, AT_SMEM>>>(p_qh, p_ql, p_kh, p_kl, p_vth, p_vtl,
                                             p_attnh, p_attnl);
    }

    // 5-6. out projection + residual
    {
        dim3 g1(RO / 128, BS / 64);
        bgemm2<1,0><<<g1, 256, B2_SMEM>>>(BS, RO, DD, p_attnh, p_attnl,
            p_wh + WOFF_OV, p_wl + WOFF_OV, nullptr, nullptr, nullptr, p_tmph, p_tmpl);
        dim3 g2(DD / 128, BS / 64);
        bgemm2<0,2><<<g2, 256, B2_SMEM>>>(BS, DD, RO, p_tmph, p_tmpl,
            p_wh + WOFF_OU, p_wl + WOFF_OU, out_bias, hidden, p_h, nullptr, nullptr);
    }

    // 7. LN2 -> bf16 hi/lo
    ln_kernel<<<BS, 256>>>(p_h, ln2_w, ln2_b, p_normh, p_norml);

    // 8-9. FC1 + bias + exact GELU
    {
        dim3 g1(RF / 128, BS / 64);
        bgemm2<1,0><<<g1, 256, B2_SMEM>>>(BS, RF, DD, p_normh, p_norml,
            p_wh + WOFF_F1V, p_wl + WOFF_F1V, nullptr, nullptr, nullptr, p_tmph, p_tmpl);
        dim3 g2(INTER / 128, BS / 64);
        bgemm2<1,1><<<g2, 256, B2_SMEM>>>(BS, INTER, RF, p_tmph, p_tmpl,
            p_wh + WOFF_F1U, p_wl + WOFF_F1U, fc1_bias, nullptr, nullptr, p_ffh, p_ffl);
    }

    // 10-11. FC2 + bias + residual -> out
    {
        dim3 g1(RF / 128, BS / 64);
        bgemm2<1,0><<<g1, 256, B2_SMEM>>>(BS, RF, INTER, p_ffh, p_ffl,
            p_wh + WOFF_F2V, p_wl + WOFF_F2V, nullptr, nullptr, nullptr, p_tmph, p_tmpl);
        dim3 g2(DD / 128, BS / 64);
        bgemm2<0,2><<<g2, 256, B2_SMEM>>>(BS, DD, RF, p_tmph, p_tmpl,
            p_wh + WOFF_F2U, p_wl + WOFF_F2U, fc2_bias, p_h, out, nullptr, nullptr);
    }
    (void)in_sizes; (void)n_in; (void)out_size;
}